// round 7
// baseline (speedup 1.0000x reference)
#include <cuda_runtime.h>

#define NB 2
#define P  8192
#define HH 48
#define WW 48
#define RH 95
#define RW 95
#define QQ (RH*RW)          // 9025
#define TILE 2048           // SoA tile: 4 arrays x 2048 floats = 32KB
#define BLK 1024
#define RPT 2               // a-points per thread (strided by BLK)
#define APC (BLK*RPT)       // 2048 a-points per CTA
#define NSPLIT 8            // b-cloud splits

#define XB_A (P/APC)                    // 4 x-blocks per batch, dir A
#define XB_B ((QQ + APC - 1)/APC)       // 5 x-blocks per batch, dir B
#define CTAS_A (NSPLIT*NB*XB_A)         // 64
#define CTAS_B (NSPLIT*NB*XB_B)         // 80
#define GRID (CTAS_A + CTAS_B)          // 144 (<= 148 SMs: one wave, co-resident)

#define NA_TOT (NB*P)       // 16384
#define NBQ_TOT (NB*QQ)     // 18050
#define FIN_ITEMS (NA_TOT + NBQ_TOT)    // 34434
#define FIN_CHUNK ((FIN_ITEMS + GRID - 1)/GRID)  // 240

// scratch (allocation-free rule: __device__ globals)
__device__ float4 g_mesh[NBQ_TOT];
__device__ float4 g_pc[NA_TOT];
__device__ float  g_bestA[NSPLIT][NA_TOT];   // per-split max_s for pc->mesh
__device__ float  g_bestB[NSPLIT][NBQ_TOT];  // per-split max_s for mesh->pc
__device__ float  g_fpart[GRID];
__device__ int    g_bar[3];                  // spin barrier counters (reset at end)

// ---------------------------------------------------------------------------
// f32x2 packed helpers
// ---------------------------------------------------------------------------
__device__ __forceinline__ unsigned long long fma2(unsigned long long a,
                                                   unsigned long long b,
                                                   unsigned long long c)
{
    unsigned long long d;
    asm("fma.rn.f32x2 %0, %1, %2, %3;" : "=l"(d) : "l"(a), "l"(b), "l"(c));
    return d;
}
__device__ __forceinline__ unsigned long long pack2(float x, float y)
{
    unsigned long long r;
    asm("mov.b64 %0, {%1,%2};" : "=l"(r) : "f"(x), "f"(y));
    return r;
}
__device__ __forceinline__ float2 u2f(unsigned long long v)
{
    float2 r;
    asm("mov.b64 {%0,%1}, %2;" : "=f"(r.x), "=f"(r.y) : "l"(v));
    return r;
}

// ---------------------------------------------------------------------------
// grid-wide spin barrier. Valid because GRID <= #SMs at occupancy 1 -> all
// CTAs co-resident in wave 1. Writer side: threadfence (device-visible) then
// arrive; reader side: tid0 spins, threadfence (CCTL.IVALL invalidates L1D),
// syncthreads releases the block.
// ---------------------------------------------------------------------------
__device__ __forceinline__ void grid_barrier(int* ctr)
{
    __threadfence();
    __syncthreads();
    if (threadIdx.x == 0) {
        atomicAdd(ctr, 1);
        while (*(volatile int*)ctr < GRID) { }
        __threadfence();
    }
    __syncthreads();
}

// ---------------------------------------------------------------------------
// One chamfer direction over one b-split.
//   s = a.b - 0.5|b|^2 ; best = max_b s  (min_d formed in finalize phase)
// ---------------------------------------------------------------------------
__device__ __forceinline__ void chamfer_quad(
    unsigned long long ax0, unsigned long long ay0, unsigned long long az0,
    unsigned long long ax1, unsigned long long ay1, unsigned long long az1,
    const float* sbx, const float* sby, const float* sbz, const float* sbw,
    int t, float& m0a, float& m0b, float& m1a, float& m1b)
{
    ulonglong2 X = *(const ulonglong2*)(sbx + t);
    ulonglong2 Y = *(const ulonglong2*)(sby + t);
    ulonglong2 Z = *(const ulonglong2*)(sbz + t);
    ulonglong2 W = *(const ulonglong2*)(sbw + t);

    unsigned long long s;
    float2 f;
    s = fma2(az0, Z.x, W.x); s = fma2(ay0, Y.x, s); s = fma2(ax0, X.x, s);
    f = u2f(s); m0a = fmaxf(m0a, f.x); m0b = fmaxf(m0b, f.y);
    s = fma2(az0, Z.y, W.y); s = fma2(ay0, Y.y, s); s = fma2(ax0, X.y, s);
    f = u2f(s); m0a = fmaxf(m0a, f.x); m0b = fmaxf(m0b, f.y);
    s = fma2(az1, Z.x, W.x); s = fma2(ay1, Y.x, s); s = fma2(ax1, X.x, s);
    f = u2f(s); m1a = fmaxf(m1a, f.x); m1b = fmaxf(m1b, f.y);
    s = fma2(az1, Z.y, W.y); s = fma2(ay1, Y.y, s); s = fma2(ax1, X.y, s);
    f = u2f(s); m1a = fmaxf(m1a, f.x); m1b = fmaxf(m1b, f.y);
}

__device__ __forceinline__ void chamfer_dir(const float4* __restrict__ An,
                                            int nA, int a_off,
                                            const float4* __restrict__ Bn,
                                            int b_lo, int b_hi,
                                            float* __restrict__ best_out,
                                            float* sbx, float* sby,
                                            float* sbz, float* sbw)
{
    int tid = threadIdx.x;
    int i0 = a_off + tid;
    int i1 = a_off + BLK + tid;
    int j0 = i0 < nA ? i0 : nA - 1;
    int j1 = i1 < nA ? i1 : nA - 1;
    float4 a0 = An[j0];
    float4 a1 = An[j1];

    unsigned long long ax0 = pack2(a0.x, a0.x), ay0 = pack2(a0.y, a0.y), az0 = pack2(a0.z, a0.z);
    unsigned long long ax1 = pack2(a1.x, a1.x), ay1 = pack2(a1.y, a1.y), az1 = pack2(a1.z, a1.z);

    float m0a = -3.0e38f, m0b = -3.0e38f;
    float m1a = -3.0e38f, m1b = -3.0e38f;

    for (int q0 = b_lo; q0 < b_hi; q0 += TILE) {
        int cnt  = min(TILE, b_hi - q0);
        int cntp = (cnt + 7) & ~7;           // pad to multiple of 8
        __syncthreads();
        for (int t = tid; t < cntp; t += BLK) {
            if (t < cnt) {
                float4 b = Bn[q0 + t];
                sbx[t] = b.x; sby[t] = b.y; sbz[t] = b.z; sbw[t] = -b.w;
            } else {
                sbx[t] = 0.0f; sby[t] = 0.0f; sbz[t] = 0.0f; sbw[t] = -3.0e38f;
            }
        }
        __syncthreads();

        #pragma unroll 1
        for (int t = 0; t < cntp; t += 8) {
            chamfer_quad(ax0, ay0, az0, ax1, ay1, az1,
                         sbx, sby, sbz, sbw, t,     m0a, m0b, m1a, m1b);
            chamfer_quad(ax0, ay0, az0, ax1, ay1, az1,
                         sbx, sby, sbz, sbw, t + 4, m0a, m0b, m1a, m1b);
        }
    }

    if (i0 < nA) best_out[i0] = fmaxf(m0a, m0b);
    if (i1 < nA) best_out[i1] = fmaxf(m1a, m1b);
}

// ---------------------------------------------------------------------------
// Fused persistent kernel: prep | barrier | chamfer | barrier | finalize
// ---------------------------------------------------------------------------
__global__ void __launch_bounds__(BLK, 1) fused_kernel(
    const float* __restrict__ verts,
    const float* __restrict__ pc,
    float* __restrict__ out)
{
    __shared__ __align__(16) float sbx[TILE];
    __shared__ __align__(16) float sby[TILE];
    __shared__ __align__(16) float sbz[TILE];
    __shared__ __align__(16) float sbw[TILE];
    __shared__ float sh[32];

    int bid = blockIdx.x;
    int tid = threadIdx.x;

    // ---- phase 0: prep (each thread handles <=1 item) ----
    {
        int gid = bid * BLK + tid;
        if (gid < NBQ_TOT) {
            int n = gid / QQ;
            int r = gid % QQ;
            int i = r / RW, j = r % RW;
            int i0 = i >> 1, j0 = j >> 1;
            int oi = i & 1,  oj = j & 1;
            const float* base = verts + n * 3 * HH * WW;
            float vv[3];
            #pragma unroll
            for (int c = 0; c < 3; c++) {
                const float* pl = base + c * HH * WW;
                float v00 = pl[i0*WW + j0];
                float top = v00;
                if (oj) top = 0.5f * (v00 + pl[i0*WW + j0 + 1]);
                float val = top;
                if (oi) {
                    float v10 = pl[(i0+1)*WW + j0];
                    float bot = v10;
                    if (oj) bot = 0.5f * (v10 + pl[(i0+1)*WW + j0 + 1]);
                    val = 0.5f * (top + bot);
                }
                vv[c] = val;
            }
            g_mesh[gid] = make_float4(vv[0], vv[1], vv[2],
                                      0.5f*(vv[0]*vv[0] + vv[1]*vv[1] + vv[2]*vv[2]));
        } else {
            int idx2 = gid - NBQ_TOT;
            if (idx2 < NA_TOT) {
                const float* s = pc + (size_t)idx2 * 3;
                float x = s[0], y = s[1], z = s[2];
                g_pc[idx2] = make_float4(x, y, z, 0.5f*(x*x + y*y + z*z));
            }
        }
    }
    grid_barrier(&g_bar[0]);

    // ---- phase 1: chamfer (directions x batches x b-splits) ----
    if (bid < CTAS_A) {
        int s   = bid / (NB*XB_A);
        int rem = bid % (NB*XB_A);
        int n   = rem / XB_A;
        int xb  = rem % XB_A;
        int b_lo = ( s      * QQ) / NSPLIT;
        int b_hi = ((s + 1) * QQ) / NSPLIT;
        chamfer_dir(g_pc + n*P, P, xb*APC,
                    g_mesh + n*QQ, b_lo, b_hi,
                    &g_bestA[s][n*P], sbx, sby, sbz, sbw);
    } else {
        int b2  = bid - CTAS_A;
        int s   = b2 / (NB*XB_B);
        int rem = b2 % (NB*XB_B);
        int n   = rem / XB_B;
        int xb  = rem % XB_B;
        int b_lo = ( s      * P) / NSPLIT;
        int b_hi = ((s + 1) * P) / NSPLIT;
        chamfer_dir(g_mesh + n*QQ, QQ, xb*APC,
                    g_pc + n*P, b_lo, b_hi,
                    &g_bestB[s][n*QQ], sbx, sby, sbz, sbw);
    }
    grid_barrier(&g_bar[1]);

    // ---- phase 2: distributed finalize (FIN_CHUNK items per CTA) ----
    float v = 0.0f;
    {
        int idx = bid * FIN_CHUNK + tid;
        if (tid < FIN_CHUNK && idx < FIN_ITEMS) {
            if (idx < NA_TOT) {
                float best = g_bestA[0][idx];
                #pragma unroll
                for (int s = 1; s < NSPLIT; s++) best = fmaxf(best, g_bestA[s][idx]);
                v = 2.0f * (g_pc[idx].w - best) * (1.0f/NA_TOT);
            } else {
                int k = idx - NA_TOT;
                float best = g_bestB[0][k];
                #pragma unroll
                for (int s = 1; s < NSPLIT; s++) best = fmaxf(best, g_bestB[s][k]);
                v = 2.0f * (g_mesh[k].w - best) * (1.0f/NBQ_TOT);
            }
        }
    }
    #pragma unroll
    for (int o = 16; o > 0; o >>= 1) v += __shfl_down_sync(0xffffffffu, v, o);
    int lane = tid & 31, wid = tid >> 5;
    if (lane == 0) sh[wid] = v;
    __syncthreads();
    if (wid == 0) {
        v = sh[lane];   // 32 warps exactly
        #pragma unroll
        for (int o = 16; o > 0; o >>= 1) v += __shfl_down_sync(0xffffffffu, v, o);
        if (lane == 0) {
            g_fpart[bid] = v;
            __threadfence();
            int t = atomicAdd(&g_bar[2], 1);
            if (t == GRID - 1) {            // last CTA: fixed-order final sum
                __threadfence();
                float r = 0.0f;
                #pragma unroll 1
                for (int i = 0; i < GRID; i++) r += g_fpart[i];
                out[0] = r;
                // reset barrier counters for the next graph replay
                g_bar[0] = 0; g_bar[1] = 0; g_bar[2] = 0;
            }
        }
    }
}

extern "C" void kernel_launch(void* const* d_in, const int* in_sizes, int n_in,
                              void* d_out, int out_size)
{
    // resolve inputs by size: vertices = 2*3*48*48 = 13824, pc = 2*8192*3 = 49152
    const float* verts = (const float*)d_in[0];
    const float* pc    = (const float*)d_in[1];
    if (n_in >= 2 && in_sizes[0] != NB*3*HH*WW) {
        verts = (const float*)d_in[1];
        pc    = (const float*)d_in[0];
    }

    fused_kernel<<<GRID, BLK>>>(verts, pc, (float*)d_out);
}

// round 8
// speedup vs baseline: 1.1247x; 1.1247x over previous
#include <cuda_runtime.h>

#define NB 2
#define P  8192
#define HH 48
#define WW 48
#define RH 95
#define RW 95
#define QQ (RH*RW)          // 9025
#define TILE 2048           // SoA tile cap: 4 arrays x 2048 floats = 32KB
#define BLK 512
#define RPT 4               // a-points per thread (strided by BLK)
#define APC (BLK*RPT)       // 2048 a-points per CTA
#define NSPLIT 8            // b-cloud splits (b-range <= 1129 < TILE)

#define XB_A (P/APC)                    // 4 x-blocks per batch, dir A
#define XB_B ((QQ + APC - 1)/APC)       // 5 x-blocks per batch, dir B
#define CTAS_A (NSPLIT*NB*XB_A)         // 64
#define CTAS_B (NSPLIT*NB*XB_B)         // 80
#define GRID (CTAS_A + CTAS_B)          // 144

#define NA_TOT (NB*P)       // 16384
#define NBQ_TOT (NB*QQ)     // 18050
#define FIN_ITEMS (NA_TOT + NBQ_TOT)    // 34434
#define FIN_BLK 1024
#define FIN_BLKS ((FIN_ITEMS + FIN_BLK - 1)/FIN_BLK)  // 34

// scratch (allocation-free rule: __device__ globals)
__device__ float g_dA[NSPLIT][NA_TOT];   // per-split min_d for pc->mesh
__device__ float g_dB[NSPLIT][NBQ_TOT];  // per-split min_d for mesh->pc
__device__ float g_fpart[FIN_BLKS];
__device__ int   g_done;                 // self-resetting completion counter

// ---------------------------------------------------------------------------
// f32x2 packed helpers
// ---------------------------------------------------------------------------
__device__ __forceinline__ unsigned long long fma2(unsigned long long a,
                                                   unsigned long long b,
                                                   unsigned long long c)
{
    unsigned long long d;
    asm("fma.rn.f32x2 %0, %1, %2, %3;" : "=l"(d) : "l"(a), "l"(b), "l"(c));
    return d;
}
__device__ __forceinline__ unsigned long long pack2(float x, float y)
{
    unsigned long long r;
    asm("mov.b64 %0, {%1,%2};" : "=l"(r) : "f"(x), "f"(y));
    return r;
}
__device__ __forceinline__ float2 u2f(unsigned long long v)
{
    float2 r;
    asm("mov.b64 {%0,%1}, %2;" : "=f"(r.x), "=f"(r.y) : "l"(v));
    return r;
}

// ---------------------------------------------------------------------------
// midpoint-bilinear refine of mesh point r (row-major over RH x RW) for batch n
// ---------------------------------------------------------------------------
__device__ __forceinline__ float4 refine_point(const float* __restrict__ verts,
                                               int n, int r)
{
    int i = r / RW, j = r % RW;
    int i0 = i >> 1, j0 = j >> 1;
    int oi = i & 1,  oj = j & 1;
    const float* base = verts + n * 3 * HH * WW;
    float vv[3];
    #pragma unroll
    for (int c = 0; c < 3; c++) {
        const float* pl = base + c * HH * WW;
        float v00 = pl[i0*WW + j0];
        float top = v00;
        if (oj) top = 0.5f * (v00 + pl[i0*WW + j0 + 1]);
        float val = top;
        if (oi) {
            float v10 = pl[(i0+1)*WW + j0];
            float bot = v10;
            if (oj) bot = 0.5f * (v10 + pl[(i0+1)*WW + j0 + 1]);
            val = 0.5f * (top + bot);
        }
        vv[c] = val;
    }
    return make_float4(vv[0], vv[1], vv[2],
                       0.5f*(vv[0]*vv[0] + vv[1]*vv[1] + vv[2]*vv[2]));
}

// ---------------------------------------------------------------------------
// Self-contained chamfer CTA: prep a-points (registers) + b-tile (smem SoA),
// scan, write per-split min_d. dirA: a=pc, b=mesh. dirB: a=mesh, b=pc.
//   s = a.b - 0.5|b|^2 ; min_d = 2*(0.5|a|^2 - max_b s)
// ---------------------------------------------------------------------------
__global__ void __launch_bounds__(BLK, 1) chamfer_kernel(
    const float* __restrict__ verts,
    const float* __restrict__ pc)
{
    __shared__ __align__(16) float sbx[TILE];
    __shared__ __align__(16) float sby[TILE];
    __shared__ __align__(16) float sbz[TILE];
    __shared__ __align__(16) float sbw[TILE];

    int bid = blockIdx.x;
    int tid = threadIdx.x;

    int dirA = (bid < CTAS_A);
    int s, n, xb, nA, b_lo, b_hi;
    if (dirA) {
        s   = bid / (NB*XB_A);
        int rem = bid % (NB*XB_A);
        n   = rem / XB_A;
        xb  = rem % XB_A;
        nA  = P;
        b_lo = ( s      * QQ) / NSPLIT;
        b_hi = ((s + 1) * QQ) / NSPLIT;
    } else {
        int b2 = bid - CTAS_A;
        s   = b2 / (NB*XB_B);
        int rem = b2 % (NB*XB_B);
        n   = rem / XB_B;
        xb  = rem % XB_B;
        nA  = QQ;
        b_lo = ( s      * P) / NSPLIT;
        b_hi = ((s + 1) * P) / NSPLIT;
    }
    int a_off = xb * APC;

    // ---- fill b-tile (SoA, negated half-norm; pad to multiple of 8) ----
    int cnt  = b_hi - b_lo;
    int cntp = (cnt + 7) & ~7;
    for (int t = tid; t < cntp; t += BLK) {
        if (t < cnt) {
            float4 b;
            if (dirA) b = refine_point(verts, n, b_lo + t);
            else {
                const float* sp = pc + ((size_t)n * P + b_lo + t) * 3;
                float x = sp[0], y = sp[1], z = sp[2];
                b = make_float4(x, y, z, 0.5f*(x*x + y*y + z*z));
            }
            sbx[t] = b.x; sby[t] = b.y; sbz[t] = b.z; sbw[t] = -b.w;
        } else {
            sbx[t] = 0.0f; sby[t] = 0.0f; sbz[t] = 0.0f; sbw[t] = -3.0e38f;
        }
    }

    // ---- load a-points into registers (while tile fills) ----
    unsigned long long AX[RPT], AY[RPT], AZ[RPT];
    float AW[RPT];
    #pragma unroll
    for (int r = 0; r < RPT; r++) {
        int i = a_off + r * BLK + tid;
        int j = i < nA ? i : nA - 1;
        float4 a;
        if (dirA) {
            const float* sp = pc + ((size_t)n * P + j) * 3;
            float x = sp[0], y = sp[1], z = sp[2];
            a = make_float4(x, y, z, 0.5f*(x*x + y*y + z*z));
        } else {
            a = refine_point(verts, n, j);
        }
        AX[r] = pack2(a.x, a.x);
        AY[r] = pack2(a.y, a.y);
        AZ[r] = pack2(a.z, a.z);
        AW[r] = a.w;
    }

    float mA[RPT], mB[RPT];
    #pragma unroll
    for (int r = 0; r < RPT; r++) { mA[r] = -3.0e38f; mB[r] = -3.0e38f; }

    __syncthreads();

    // ---- scan: 4 b-points per step, all RPT a-points ----
    #pragma unroll 2
    for (int t = 0; t < cntp; t += 4) {
        ulonglong2 X = *(const ulonglong2*)(sbx + t);
        ulonglong2 Y = *(const ulonglong2*)(sby + t);
        ulonglong2 Z = *(const ulonglong2*)(sbz + t);
        ulonglong2 W = *(const ulonglong2*)(sbw + t);
        #pragma unroll
        for (int r = 0; r < RPT; r++) {
            unsigned long long v;
            float2 f;
            v = fma2(AZ[r], Z.x, W.x); v = fma2(AY[r], Y.x, v); v = fma2(AX[r], X.x, v);
            f = u2f(v); mA[r] = fmaxf(mA[r], f.x); mB[r] = fmaxf(mB[r], f.y);
            v = fma2(AZ[r], Z.y, W.y); v = fma2(AY[r], Y.y, v); v = fma2(AX[r], X.y, v);
            f = u2f(v); mA[r] = fmaxf(mA[r], f.x); mB[r] = fmaxf(mB[r], f.y);
        }
    }

    // ---- write per-split min_d ----
    float* out = dirA ? &g_dA[s][n*P] : &g_dB[s][n*QQ];
    #pragma unroll
    for (int r = 0; r < RPT; r++) {
        int i = a_off + r * BLK + tid;
        if (i < nA)
            out[i] = 2.0f * (AW[r] - fmaxf(mA[r], mB[r]));
    }
}

// ---------------------------------------------------------------------------
// finalize: min over splits, mean over points, last-block final sum
// (counter self-resets for graph replay)
// ---------------------------------------------------------------------------
__global__ void finalize_kernel(float* __restrict__ out)
{
    __shared__ float sh[32];
    __shared__ int   s_last;
    int idx = blockIdx.x * FIN_BLK + threadIdx.x;
    float v = 0.0f;
    if (idx < NA_TOT) {
        float d = g_dA[0][idx];
        #pragma unroll
        for (int s = 1; s < NSPLIT; s++) d = fminf(d, g_dA[s][idx]);
        v = d * (1.0f/NA_TOT);
    } else if (idx < FIN_ITEMS) {
        int k = idx - NA_TOT;
        float d = g_dB[0][k];
        #pragma unroll
        for (int s = 1; s < NSPLIT; s++) d = fminf(d, g_dB[s][k]);
        v = d * (1.0f/NBQ_TOT);
    }
    #pragma unroll
    for (int o = 16; o > 0; o >>= 1) v += __shfl_down_sync(0xffffffffu, v, o);
    int lane = threadIdx.x & 31, wid = threadIdx.x >> 5;
    if (lane == 0) sh[wid] = v;
    __syncthreads();
    if (wid == 0) {
        v = sh[lane];   // exactly 32 warps
        #pragma unroll
        for (int o = 16; o > 0; o >>= 1) v += __shfl_down_sync(0xffffffffu, v, o);
        if (lane == 0) {
            g_fpart[blockIdx.x] = v;
            __threadfence();
            int t = atomicAdd(&g_done, 1);
            s_last = (t == FIN_BLKS - 1);
        }
    }
    __syncthreads();
    if (s_last && wid == 0 && lane == 0) {
        __threadfence();
        float r = 0.0f;
        #pragma unroll 1
        for (int i = 0; i < FIN_BLKS; i++) r += g_fpart[i];
        out[0] = r;
        g_done = 0;     // reset for next graph replay
    }
}

extern "C" void kernel_launch(void* const* d_in, const int* in_sizes, int n_in,
                              void* d_out, int out_size)
{
    // resolve inputs by size: vertices = 2*3*48*48 = 13824, pc = 2*8192*3 = 49152
    const float* verts = (const float*)d_in[0];
    const float* pc    = (const float*)d_in[1];
    if (n_in >= 2 && in_sizes[0] != NB*3*HH*WW) {
        verts = (const float*)d_in[1];
        pc    = (const float*)d_in[0];
    }

    chamfer_kernel<<<GRID, BLK>>>(verts, pc);
    finalize_kernel<<<FIN_BLKS, FIN_BLK>>>((float*)d_out);
}

// round 10
// speedup vs baseline: 1.1838x; 1.0526x over previous
#include <cuda_runtime.h>

#define NB 2
#define P  8192
#define HH 48
#define WW 48
#define RH 95
#define RW 95
#define QQ (RH*RW)          // 9025
#define TILE 2048           // SoA tile cap: 4 arrays x 2048 floats = 32KB
#define BLK 512
#define RPT 4               // a-points per thread (strided by BLK)
#define APC (BLK*RPT)       // 2048 a-points per CTA
#define NSPLIT 8            // b-cloud splits (b-range <= 1129 < TILE)

#define XB_A (P/APC)                    // 4 x-blocks per batch, dir A
#define XB_B ((QQ + APC - 1)/APC)       // 5 x-blocks per batch, dir B
#define CTAS_A (NSPLIT*NB*XB_A)         // 64
#define CTAS_B (NSPLIT*NB*XB_B)         // 80
#define GRID (CTAS_A + CTAS_B)          // 144

#define NGRP_A (NB*XB_A)    // 8
#define NGRP_B (NB*XB_B)    // 10
#define NGRP (NGRP_A + NGRP_B)          // 18

#define NA_TOT (NB*P)       // 16384
#define NBQ_TOT (NB*QQ)     // 18050

// scratch (allocation-free rule: __device__ globals; zero-init, self-resetting)
__device__ float g_dA[NSPLIT][NA_TOT];   // per-split min_d for pc->mesh
__device__ float g_dB[NSPLIT][NBQ_TOT];  // per-split min_d for mesh->pc
__device__ float g_gpart[NGRP];
__device__ int   g_gcnt[NGRP];
__device__ int   g_done;

// ---------------------------------------------------------------------------
// f32x2 packed helpers
// ---------------------------------------------------------------------------
__device__ __forceinline__ unsigned long long fma2(unsigned long long a,
                                                   unsigned long long b,
                                                   unsigned long long c)
{
    unsigned long long d;
    asm("fma.rn.f32x2 %0, %1, %2, %3;" : "=l"(d) : "l"(a), "l"(b), "l"(c));
    return d;
}
__device__ __forceinline__ unsigned long long pack2(float x, float y)
{
    unsigned long long r;
    asm("mov.b64 %0, {%1,%2};" : "=l"(r) : "f"(x), "f"(y));
    return r;
}
__device__ __forceinline__ float2 u2f(unsigned long long v)
{
    float2 r;
    asm("mov.b64 {%0,%1}, %2;" : "=f"(r.x), "=f"(r.y) : "l"(v));
    return r;
}

// ---------------------------------------------------------------------------
// midpoint-bilinear refine of mesh point r (row-major over RH x RW), batch n
// ---------------------------------------------------------------------------
__device__ __forceinline__ float4 refine_point(const float* __restrict__ verts,
                                               int n, int r)
{
    int i = r / RW, j = r % RW;
    int i0 = i >> 1, j0 = j >> 1;
    int oi = i & 1,  oj = j & 1;
    const float* base = verts + n * 3 * HH * WW;
    float vv[3];
    #pragma unroll
    for (int c = 0; c < 3; c++) {
        const float* pl = base + c * HH * WW;
        float v00 = pl[i0*WW + j0];
        float top = v00;
        if (oj) top = 0.5f * (v00 + pl[i0*WW + j0 + 1]);
        float val = top;
        if (oi) {
            float v10 = pl[(i0+1)*WW + j0];
            float bot = v10;
            if (oj) bot = 0.5f * (v10 + pl[(i0+1)*WW + j0 + 1]);
            val = 0.5f * (top + bot);
        }
        vv[c] = val;
    }
    return make_float4(vv[0], vv[1], vv[2],
                       0.5f*(vv[0]*vv[0] + vv[1]*vv[1] + vv[2]*vv[2]));
}

// ---------------------------------------------------------------------------
// Fused: self-prep chamfer + hierarchical in-kernel finalize.
// dirA: a=pc, b=mesh. dirB: a=mesh, b=pc.
//   s = a.b - 0.5|b|^2 ; min_d = 2*(0.5|a|^2 - max_b s)
// ---------------------------------------------------------------------------
__global__ void __launch_bounds__(BLK, 1) chamfer_fused_kernel(
    const float* __restrict__ verts,
    const float* __restrict__ pc,
    float* __restrict__ outp)
{
    __shared__ __align__(16) float sbx[TILE];
    __shared__ __align__(16) float sby[TILE];
    __shared__ __align__(16) float sbz[TILE];
    __shared__ __align__(16) float sbw[TILE];
    __shared__ float sh[16];
    __shared__ int   s_gl, s_fin;

    int bid = blockIdx.x;
    int tid = threadIdx.x;

    int dirA = (bid < CTAS_A);
    int s, n, xb, nA, b_lo, b_hi, gid;
    if (dirA) {
        s   = bid / (NB*XB_A);
        int rem = bid % (NB*XB_A);
        n   = rem / XB_A;
        xb  = rem % XB_A;
        nA  = P;
        b_lo = ( s      * QQ) / NSPLIT;
        b_hi = ((s + 1) * QQ) / NSPLIT;
        gid  = n * XB_A + xb;
    } else {
        int b2 = bid - CTAS_A;
        s   = b2 / (NB*XB_B);
        int rem = b2 % (NB*XB_B);
        n   = rem / XB_B;
        xb  = rem % XB_B;
        nA  = QQ;
        b_lo = ( s      * P) / NSPLIT;
        b_hi = ((s + 1) * P) / NSPLIT;
        gid  = NGRP_A + n * XB_B + xb;
    }
    int a_off = xb * APC;

    // ---- fill b-tile (SoA, negated half-norm; pad to multiple of 8) ----
    int cnt  = b_hi - b_lo;
    int cntp = (cnt + 7) & ~7;
    for (int t = tid; t < cntp; t += BLK) {
        if (t < cnt) {
            float4 b;
            if (dirA) b = refine_point(verts, n, b_lo + t);
            else {
                const float* sp = pc + ((size_t)n * P + b_lo + t) * 3;
                float x = sp[0], y = sp[1], z = sp[2];
                b = make_float4(x, y, z, 0.5f*(x*x + y*y + z*z));
            }
            sbx[t] = b.x; sby[t] = b.y; sbz[t] = b.z; sbw[t] = -b.w;
        } else {
            sbx[t] = 0.0f; sby[t] = 0.0f; sbz[t] = 0.0f; sbw[t] = -3.0e38f;
        }
    }

    // ---- load a-points into registers ----
    unsigned long long AX[RPT], AY[RPT], AZ[RPT];
    float AW[RPT];
    #pragma unroll
    for (int r = 0; r < RPT; r++) {
        int i = a_off + r * BLK + tid;
        int j = i < nA ? i : nA - 1;
        float4 a;
        if (dirA) {
            const float* sp = pc + ((size_t)n * P + j) * 3;
            float x = sp[0], y = sp[1], z = sp[2];
            a = make_float4(x, y, z, 0.5f*(x*x + y*y + z*z));
        } else {
            a = refine_point(verts, n, j);
        }
        AX[r] = pack2(a.x, a.x);
        AY[r] = pack2(a.y, a.y);
        AZ[r] = pack2(a.z, a.z);
        AW[r] = a.w;
    }

    float mA[RPT], mB[RPT];
    #pragma unroll
    for (int r = 0; r < RPT; r++) { mA[r] = -3.0e38f; mB[r] = -3.0e38f; }

    __syncthreads();

    // ---- scan: 4 b-points per step, all RPT a-points ----
    #pragma unroll 2
    for (int t = 0; t < cntp; t += 4) {
        ulonglong2 X = *(const ulonglong2*)(sbx + t);
        ulonglong2 Y = *(const ulonglong2*)(sby + t);
        ulonglong2 Z = *(const ulonglong2*)(sbz + t);
        ulonglong2 W = *(const ulonglong2*)(sbw + t);
        #pragma unroll
        for (int r = 0; r < RPT; r++) {
            unsigned long long v;
            float2 f;
            v = fma2(AZ[r], Z.x, W.x); v = fma2(AY[r], Y.x, v); v = fma2(AX[r], X.x, v);
            f = u2f(v); mA[r] = fmaxf(mA[r], f.x); mB[r] = fmaxf(mB[r], f.y);
            v = fma2(AZ[r], Z.y, W.y); v = fma2(AY[r], Y.y, v); v = fma2(AX[r], X.y, v);
            f = u2f(v); mA[r] = fmaxf(mA[r], f.x); mB[r] = fmaxf(mB[r], f.y);
        }
    }

    // ---- write per-split min_d ----
    {
        float* out = dirA ? &g_dA[s][n*P] : &g_dB[s][n*QQ];
        #pragma unroll
        for (int r = 0; r < RPT; r++) {
            int i = a_off + r * BLK + tid;
            if (i < nA)
                out[i] = 2.0f * (AW[r] - fmaxf(mA[r], mB[r]));
        }
    }

    // ---- group arrival: last of the NSPLIT CTAs combines this a-range ----
    __threadfence();
    __syncthreads();
    if (tid == 0) {
        int t = atomicAdd(&g_gcnt[gid], 1);
        s_gl = (t == NSPLIT - 1);
    }
    __syncthreads();
    if (!s_gl) return;
    __threadfence();        // acquire: see all split writes

    // group finalize: min over splits, weighted partial sum over this range
    {
        float v = 0.0f;
        if (dirA) {
            int base = n*P + a_off;
            float w = 1.0f / NA_TOT;
            for (int k = tid; k < APC; k += BLK) {
                int idx = base + k;
                float d = g_dA[0][idx];
                #pragma unroll
                for (int q = 1; q < NSPLIT; q++) d = fminf(d, g_dA[q][idx]);
                v += d * w;
            }
        } else {
            int base = n*QQ + a_off;
            int count = (QQ - a_off < APC) ? (QQ - a_off) : APC;
            float w = 1.0f / NBQ_TOT;
            for (int k = tid; k < count; k += BLK) {
                int idx = base + k;
                float d = g_dB[0][idx];
                #pragma unroll
                for (int q = 1; q < NSPLIT; q++) d = fminf(d, g_dB[q][idx]);
                v += d * w;
            }
        }
        // block reduce (16 warps)
        #pragma unroll
        for (int o = 16; o > 0; o >>= 1) v += __shfl_down_sync(0xffffffffu, v, o);
        int lane = tid & 31, wid = tid >> 5;
        if (lane == 0) sh[wid] = v;
        __syncthreads();
        if (wid == 0) {
            v = (lane < 16) ? sh[lane] : 0.0f;
            #pragma unroll
            for (int o = 8; o > 0; o >>= 1) v += __shfl_down_sync(0xffffffffu, v, o);
            if (lane == 0) {
                g_gpart[gid] = v;
                g_gcnt[gid] = 0;          // reset for next graph replay
                __threadfence();
                int t = atomicAdd(&g_done, 1);
                s_fin = (t == NGRP - 1);
            }
        }
    }
    __syncthreads();

    // ---- global finalize: last group sums NGRP partials in fixed order ----
    if (s_fin && tid == 0) {
        __threadfence();
        float r = 0.0f;
        #pragma unroll
        for (int i = 0; i < NGRP; i++) r += g_gpart[i];
        outp[0] = r;
        g_done = 0;                        // reset for next graph replay
    }
}

extern "C" void kernel_launch(void* const* d_in, const int* in_sizes, int n_in,
                              void* d_out, int out_size)
{
    // resolve inputs by size: vertices = 2*3*48*48 = 13824, pc = 2*8192*3 = 49152
    const float* verts = (const float*)d_in[0];
    const float* pc    = (const float*)d_in[1];
    if (n_in >= 2 && in_sizes[0] != NB*3*HH*WW) {
        verts = (const float*)d_in[1];
        pc    = (const float*)d_in[0];
    }

    chamfer_fused_kernel<<<GRID, BLK>>>(verts, pc, (float*)d_out);
}

// round 12
// speedup vs baseline: 1.2271x; 1.0365x over previous
#include <cuda_runtime.h>

#define NB 2
#define P  8192
#define HH 48
#define WW 48
#define RH 95
#define RW 95
#define QQ (RH*RW)          // 9025
#define TILE 768            // SoA tile: 4 arrays x 768 floats = 12.2KB (b-range <= 753)
#define BLK 384
#define RPT 4               // a-points per thread (strided by BLK)
#define APC (BLK*RPT)       // 1536 a-points per CTA
#define NSPLIT 12           // b-cloud splits

#define XB_A ((P  + APC - 1)/APC)       // 6 x-blocks per batch, dir A
#define XB_B ((QQ + APC - 1)/APC)       // 6 x-blocks per batch, dir B
#define CTAS_A (NSPLIT*NB*XB_A)         // 144
#define CTAS_B (NSPLIT*NB*XB_B)         // 144
#define GRID (CTAS_A + CTAS_B)          // 288  (2 CTAs/SM on 144 SMs)

#define NGRP_A (NB*XB_A)    // 12
#define NGRP_B (NB*XB_B)    // 12
#define NGRP (NGRP_A + NGRP_B)          // 24

#define NA_TOT (NB*P)       // 16384
#define NBQ_TOT (NB*QQ)     // 18050

// scratch (allocation-free rule: __device__ globals; zero-init, self-resetting)
__device__ float g_dA[NSPLIT][NA_TOT];   // per-split min_d for pc->mesh
__device__ float g_dB[NSPLIT][NBQ_TOT];  // per-split min_d for mesh->pc
__device__ float g_gpart[NGRP];
__device__ int   g_gcnt[NGRP];
__device__ int   g_done;

// ---------------------------------------------------------------------------
// f32x2 packed helpers
// ---------------------------------------------------------------------------
__device__ __forceinline__ unsigned long long fma2(unsigned long long a,
                                                   unsigned long long b,
                                                   unsigned long long c)
{
    unsigned long long d;
    asm("fma.rn.f32x2 %0, %1, %2, %3;" : "=l"(d) : "l"(a), "l"(b), "l"(c));
    return d;
}
__device__ __forceinline__ unsigned long long pack2(float x, float y)
{
    unsigned long long r;
    asm("mov.b64 %0, {%1,%2};" : "=l"(r) : "f"(x), "f"(y));
    return r;
}
__device__ __forceinline__ float2 u2f(unsigned long long v)
{
    float2 r;
    asm("mov.b64 {%0,%1}, %2;" : "=f"(r.x), "=f"(r.y) : "l"(v));
    return r;
}

// ---------------------------------------------------------------------------
// midpoint-bilinear refine of mesh point r (row-major over RH x RW), batch n
// ---------------------------------------------------------------------------
__device__ __forceinline__ float4 refine_point(const float* __restrict__ verts,
                                               int n, int r)
{
    int i = r / RW, j = r % RW;
    int i0 = i >> 1, j0 = j >> 1;
    int oi = i & 1,  oj = j & 1;
    const float* base = verts + n * 3 * HH * WW;
    float vv[3];
    #pragma unroll
    for (int c = 0; c < 3; c++) {
        const float* pl = base + c * HH * WW;
        float v00 = pl[i0*WW + j0];
        float top = v00;
        if (oj) top = 0.5f * (v00 + pl[i0*WW + j0 + 1]);
        float val = top;
        if (oi) {
            float v10 = pl[(i0+1)*WW + j0];
            float bot = v10;
            if (oj) bot = 0.5f * (v10 + pl[(i0+1)*WW + j0 + 1]);
            val = 0.5f * (top + bot);
        }
        vv[c] = val;
    }
    return make_float4(vv[0], vv[1], vv[2],
                       0.5f*(vv[0]*vv[0] + vv[1]*vv[1] + vv[2]*vv[2]));
}

// ---------------------------------------------------------------------------
// Fused: self-prep chamfer + hierarchical in-kernel finalize.
// dirA: a=pc, b=mesh. dirB: a=mesh, b=pc.
//   s = a.b - 0.5|b|^2 ; min_d = 2*(0.5|a|^2 - max_b s)
// ---------------------------------------------------------------------------
__global__ void __launch_bounds__(BLK, 2) chamfer_fused_kernel(
    const float* __restrict__ verts,
    const float* __restrict__ pc,
    float* __restrict__ outp)
{
    __shared__ __align__(16) float sbx[TILE];
    __shared__ __align__(16) float sby[TILE];
    __shared__ __align__(16) float sbz[TILE];
    __shared__ __align__(16) float sbw[TILE];
    __shared__ float sh[BLK/32];
    __shared__ int   s_gl, s_fin;

    int bid = blockIdx.x;
    int tid = threadIdx.x;

    int dirA = (bid < CTAS_A);
    int s, n, xb, nA, b_lo, b_hi, gid;
    if (dirA) {
        s   = bid / (NB*XB_A);
        int rem = bid % (NB*XB_A);
        n   = rem / XB_A;
        xb  = rem % XB_A;
        nA  = P;
        b_lo = ( s      * QQ) / NSPLIT;
        b_hi = ((s + 1) * QQ) / NSPLIT;
        gid  = n * XB_A + xb;
    } else {
        int b2 = bid - CTAS_A;
        s   = b2 / (NB*XB_B);
        int rem = b2 % (NB*XB_B);
        n   = rem / XB_B;
        xb  = rem % XB_B;
        nA  = QQ;
        b_lo = ( s      * P) / NSPLIT;
        b_hi = ((s + 1) * P) / NSPLIT;
        gid  = NGRP_A + n * XB_B + xb;
    }
    int a_off = xb * APC;

    // ---- fill b-tile (SoA, negated half-norm; pad to multiple of 8) ----
    int cnt  = b_hi - b_lo;
    int cntp = (cnt + 7) & ~7;
    for (int t = tid; t < cntp; t += BLK) {
        if (t < cnt) {
            float4 b;
            if (dirA) b = refine_point(verts, n, b_lo + t);
            else {
                const float* sp = pc + ((size_t)n * P + b_lo + t) * 3;
                float x = sp[0], y = sp[1], z = sp[2];
                b = make_float4(x, y, z, 0.5f*(x*x + y*y + z*z));
            }
            sbx[t] = b.x; sby[t] = b.y; sbz[t] = b.z; sbw[t] = -b.w;
        } else {
            sbx[t] = 0.0f; sby[t] = 0.0f; sbz[t] = 0.0f; sbw[t] = -3.0e38f;
        }
    }

    // ---- load a-points into registers ----
    unsigned long long AX[RPT], AY[RPT], AZ[RPT];
    float AW[RPT];
    #pragma unroll
    for (int r = 0; r < RPT; r++) {
        int i = a_off + r * BLK + tid;
        int j = i < nA ? i : nA - 1;
        float4 a;
        if (dirA) {
            const float* sp = pc + ((size_t)n * P + j) * 3;
            float x = sp[0], y = sp[1], z = sp[2];
            a = make_float4(x, y, z, 0.5f*(x*x + y*y + z*z));
        } else {
            a = refine_point(verts, n, j);
        }
        AX[r] = pack2(a.x, a.x);
        AY[r] = pack2(a.y, a.y);
        AZ[r] = pack2(a.z, a.z);
        AW[r] = a.w;
    }

    float mA[RPT], mB[RPT];
    #pragma unroll
    for (int r = 0; r < RPT; r++) { mA[r] = -3.0e38f; mB[r] = -3.0e38f; }

    __syncthreads();

    // ---- scan: 4 b-points per step, all RPT a-points ----
    #pragma unroll 2
    for (int t = 0; t < cntp; t += 4) {
        ulonglong2 X = *(const ulonglong2*)(sbx + t);
        ulonglong2 Y = *(const ulonglong2*)(sby + t);
        ulonglong2 Z = *(const ulonglong2*)(sbz + t);
        ulonglong2 W = *(const ulonglong2*)(sbw + t);
        #pragma unroll
        for (int r = 0; r < RPT; r++) {
            unsigned long long v;
            float2 f;
            v = fma2(AZ[r], Z.x, W.x); v = fma2(AY[r], Y.x, v); v = fma2(AX[r], X.x, v);
            f = u2f(v); mA[r] = fmaxf(mA[r], f.x); mB[r] = fmaxf(mB[r], f.y);
            v = fma2(AZ[r], Z.y, W.y); v = fma2(AY[r], Y.y, v); v = fma2(AX[r], X.y, v);
            f = u2f(v); mA[r] = fmaxf(mA[r], f.x); mB[r] = fmaxf(mB[r], f.y);
        }
    }

    // ---- write per-split min_d ----
    {
        float* out = dirA ? &g_dA[s][n*P] : &g_dB[s][n*QQ];
        #pragma unroll
        for (int r = 0; r < RPT; r++) {
            int i = a_off + r * BLK + tid;
            if (i < nA)
                out[i] = 2.0f * (AW[r] - fmaxf(mA[r], mB[r]));
        }
    }

    // ---- group arrival: last of the NSPLIT CTAs combines this a-range ----
    __threadfence();
    __syncthreads();
    if (tid == 0) {
        int t = atomicAdd(&g_gcnt[gid], 1);
        s_gl = (t == NSPLIT - 1);
    }
    __syncthreads();
    if (!s_gl) return;
    __threadfence();        // acquire: see all split writes

    // group finalize: min over splits, weighted partial sum over this a-range
    {
        float v = 0.0f;
        if (dirA) {
            int base = n*P + a_off;
            int count = (P - a_off < APC) ? (P - a_off) : APC;
            float w = 1.0f / NA_TOT;
            for (int k = tid; k < count; k += BLK) {
                int idx = base + k;
                float d = g_dA[0][idx];
                #pragma unroll
                for (int q = 1; q < NSPLIT; q++) d = fminf(d, g_dA[q][idx]);
                v += d * w;
            }
        } else {
            int base = n*QQ + a_off;
            int count = (QQ - a_off < APC) ? (QQ - a_off) : APC;
            float w = 1.0f / NBQ_TOT;
            for (int k = tid; k < count; k += BLK) {
                int idx = base + k;
                float d = g_dB[0][idx];
                #pragma unroll
                for (int q = 1; q < NSPLIT; q++) d = fminf(d, g_dB[q][idx]);
                v += d * w;
            }
        }
        // block reduce (BLK/32 = 12 warps)
        #pragma unroll
        for (int o = 16; o > 0; o >>= 1) v += __shfl_down_sync(0xffffffffu, v, o);
        int lane = tid & 31, wid = tid >> 5;
        if (lane == 0) sh[wid] = v;
        __syncthreads();
        if (wid == 0) {
            v = (lane < BLK/32) ? sh[lane] : 0.0f;
            #pragma unroll
            for (int o = 8; o > 0; o >>= 1) v += __shfl_down_sync(0xffffffffu, v, o);
            if (lane == 0) {
                g_gpart[gid] = v;
                g_gcnt[gid] = 0;          // reset for next graph replay
                __threadfence();
                int t = atomicAdd(&g_done, 1);
                s_fin = (t == NGRP - 1);
            }
        }
    }
    __syncthreads();

    // ---- global finalize: last group sums NGRP partials in fixed order ----
    if (s_fin && tid == 0) {
        __threadfence();
        float r = 0.0f;
        #pragma unroll
        for (int i = 0; i < NGRP; i++) r += g_gpart[i];
        outp[0] = r;
        g_done = 0;                        // reset for next graph replay
    }
}

extern "C" void kernel_launch(void* const* d_in, const int* in_sizes, int n_in,
                              void* d_out, int out_size)
{
    // resolve inputs by size: vertices = 2*3*48*48 = 13824, pc = 2*8192*3 = 49152
    const float* verts = (const float*)d_in[0];
    const float* pc    = (const float*)d_in[1];
    if (n_in >= 2 && in_sizes[0] != NB*3*HH*WW) {
        verts = (const float*)d_in[1];
        pc    = (const float*)d_in[0];
    }

    chamfer_fused_kernel<<<GRID, BLK>>>(verts, pc, (float*)d_out);
}